// round 2
// baseline (speedup 1.0000x reference)
#include <cuda_runtime.h>
#include <cuda_fp16.h>
#include <cstdint>

#define B_  32
#define N_  2048
#define K_  128
#define CI_ 16
#define CO_ 16
#define KD_ (K_*CO_)   // 2048

typedef unsigned long long ull;

// ---------------- scratch (device globals; no allocation allowed) ----------------
__device__ __half g_uhat[(size_t)B_ * N_ * KD_];   // [b][i][k][d]  fp16, 268MB
__device__ float  g_logits[(size_t)B_ * N_ * K_];  // [b][i][k]
__device__ float  g_t[3][B_ * KD_];                // per-iter weighted sums  [b][k][d]
__device__ float  g_S[2][B_ * K_];                 // per-iter coupling sums  [b][k]
__device__ float  g_v[B_ * KD_];                   // current v               [b][k][d]
__device__ float  g_vn[B_ * K_];                   // ||v||^2                 [b][k]

// ---------------- f32x2 packed helpers (Blackwell) ----------------
__device__ __forceinline__ ull pack2(float a, float b) {
    ull r; asm("mov.b64 %0, {%1,%2};" : "=l"(r) : "f"(a), "f"(b)); return r;
}
__device__ __forceinline__ void unpack2(ull v, float& a, float& b) {
    asm("mov.b64 {%0,%1}, %2;" : "=f"(a), "=f"(b) : "l"(v));
}
__device__ __forceinline__ void ffma2(ull& d, ull a, ull b) {
    asm("fma.rn.f32x2 %0, %1, %2, %0;" : "+l"(d) : "l"(a), "l"(b));
}
__device__ __forceinline__ void fadd2(ull& d, ull a) {
    asm("add.rn.f32x2 %0, %0, %1;" : "+l"(d) : "l"(a));
}

// Robust label fetch: works whether the harness serialized labels as int32 or
// int64. labels = arange(128); an int32 buffer has int32-view[1]==1, an int64
// (little-endian) buffer has int32-view[1]==0 (high word of element 0).
__device__ __forceinline__ int load_label(const void* labels, int k) {
    const int* p32 = (const int*)labels;
    if (p32[1] == 1) return p32[k];
    return (int)((const long long*)labels)[k];
}

// ---------------- init: zero accumulators ----------------
__global__ void k_init() {
    int idx = blockIdx.x * 256 + threadIdx.x;
    if (idx < 3 * B_ * KD_) (&g_t[0][0])[idx] = 0.f;
    if (idx < 2 * B_ * K_)  (&g_S[0][0])[idx] = 0.f;
}

// ---------------- pass 1: u_hat (fp32 compute, fp16 store) + t1 = sum_i u_hat ----
// grid (128, 8), block 256. Block covers 16 i's x 256 (k,d) pairs, all 32 b.
__global__ void __launch_bounds__(256) k_pass1(const float* __restrict__ x,
                                               const void* __restrict__ labels,
                                               const float* __restrict__ W1) {
    __shared__ __align__(16) float xs[512];     // packed x pairs: [(bp*16+c)*2 + h]
    const int tid = threadIdx.x;
    const int kd  = blockIdx.y * 256 + tid;     // 0..2047
    const int k   = kd >> 4;
    const int d   = kd & 15;
    int ksrc = load_label(labels, k);
    if ((unsigned)ksrc >= (unsigned)K_) ksrc = k;   // safety clamp
    const int i0  = blockIdx.x * 16;

    ull tsum[16];
#pragma unroll
    for (int bp = 0; bp < 16; bp++) tsum[bp] = 0ull;

    for (int ii = 0; ii < 16; ii++) {
        const int i = i0 + ii;
        __syncthreads();
        // stage x[:, i, :] packed as (b even, b odd) pairs
        for (int e = tid; e < 512; e += 256) {
            int b = e >> 4, c = e & 15;
            xs[((b >> 1) * 16 + c) * 2 + (b & 1)] = x[((size_t)b * N_ + i) * CI_ + c];
        }
        __syncthreads();

        const float4* wp = reinterpret_cast<const float4*>(
            W1 + (((size_t)i * K_ + ksrc) * CO_ + d) * CI_);
        float4 w0 = wp[0], w1 = wp[1], w2 = wp[2], w3 = wp[3];
        ull wd[16];
        wd[0]=pack2(w0.x,w0.x); wd[1]=pack2(w0.y,w0.y); wd[2]=pack2(w0.z,w0.z); wd[3]=pack2(w0.w,w0.w);
        wd[4]=pack2(w1.x,w1.x); wd[5]=pack2(w1.y,w1.y); wd[6]=pack2(w1.z,w1.z); wd[7]=pack2(w1.w,w1.w);
        wd[8]=pack2(w2.x,w2.x); wd[9]=pack2(w2.y,w2.y); wd[10]=pack2(w2.z,w2.z); wd[11]=pack2(w2.w,w2.w);
        wd[12]=pack2(w3.x,w3.x); wd[13]=pack2(w3.y,w3.y); wd[14]=pack2(w3.z,w3.z); wd[15]=pack2(w3.w,w3.w);

#pragma unroll
        for (int bp = 0; bp < 16; bp++) {
            const ull* xv = reinterpret_cast<const ull*>(xs) + bp * 16;
            ull acc = 0ull;
#pragma unroll
            for (int c = 0; c < 16; c++) ffma2(acc, wd[c], xv[c]);
            fadd2(tsum[bp], acc);
            float lo, hi; unpack2(acc, lo, hi);
            g_uhat[((size_t)(2 * bp)     * N_ + i) * KD_ + kd] = __float2half_rn(lo);
            g_uhat[((size_t)(2 * bp + 1) * N_ + i) * KD_ + kd] = __float2half_rn(hi);
        }
    }
#pragma unroll
    for (int bp = 0; bp < 16; bp++) {
        float a, bb; unpack2(tsum[bp], a, bb);
        atomicAdd(&g_t[0][(2 * bp)     * KD_ + kd], a);
        atomicAdd(&g_t[0][(2 * bp + 1) * KD_ + kd], bb);
    }
}

// ---------------- finalize: v = squash(t * inv), vnorm = ||v||^2 ----------------
__global__ void k_finalize(int which) {   // which=0: t1, S=1/2048 ; which=1: t2/S2
    const int idx = blockIdx.x * 256 + threadIdx.x;   // b*K + k, 0..4095
    const float* t = g_t[which];
    float inv = (which == 0) ? (1.0f / 2048.0f) : (1.0f / g_S[0][idx]);
    const float4* tp = reinterpret_cast<const float4*>(t + idx * 16);
    float w[16]; float s2 = 0.f;
#pragma unroll
    for (int q = 0; q < 4; q++) {
        float4 tv = tp[q];
        w[q*4+0]=tv.x*inv; w[q*4+1]=tv.y*inv; w[q*4+2]=tv.z*inv; w[q*4+3]=tv.w*inv;
        s2 += w[q*4+0]*w[q*4+0] + w[q*4+1]*w[q*4+1] + w[q*4+2]*w[q*4+2] + w[q*4+3]*w[q*4+3];
    }
    float sc = sqrtf(s2) / (0.5f + s2);
    float4* vp = reinterpret_cast<float4*>(g_v + idx * 16);
#pragma unroll
    for (int q = 0; q < 4; q++) {
        float4 o; o.x=sc*w[q*4+0]; o.y=sc*w[q*4+1]; o.z=sc*w[q*4+2]; o.w=sc*w[q*4+3];
        vp[q] = o;
    }
    g_vn[idx] = sc * sc * s2;
}

// ---------------- routing pass (iteration 2 or 3) ----------------
// grid 2048 (= 32 b * 64 chunks), block 256 (8 warps, 4 i each).
template <int IT>
__global__ void __launch_bounds__(256) k_route() {
    extern __shared__ float sm[];
    float*  v_sm  = sm;                    // 2048
    float*  vn_sm = sm + 2048;             // 128
    float*  t_sm  = sm + 2176;             // 128*17 = 2176 (pitch 17: conflict-free atomics)
    float*  s_sm  = sm + 2176 + 2176;      // 128
    __half* u_sm  = reinterpret_cast<__half*>(sm + 4480);  // 8 warps * 2048 halfs

    const int tid = threadIdx.x, lane = tid & 31, warp = tid >> 5;
    const int b   = blockIdx.x >> 6;
    const int ch  = blockIdx.x & 63;

    for (int e = tid; e < 2048; e += 256) v_sm[e] = g_v[b * KD_ + e];
    if (tid < 128) { vn_sm[tid] = g_vn[b * K_ + tid]; s_sm[tid] = 0.f; }
    for (int e = tid; e < 2176; e += 256) t_sm[e] = 0.f;
    __syncthreads();

    __half* us = u_sm + warp * 2048;
    for (int q = 0; q < 4; q++) {
        const int i = ch * 32 + warp * 4 + q;
        // stage 4KB contiguous u_hat[b][i][:][:] into SMEM (coalesced)
        const uint4* src = reinterpret_cast<const uint4*>(g_uhat + ((size_t)b * N_ + i) * KD_);
        uint4* dst = reinterpret_cast<uint4*>(us);
#pragma unroll
        for (int c = 0; c < 8; c++) dst[c * 32 + lane] = src[c * 32 + lane];
        __syncwarp();

        float lg[4];
#pragma unroll
        for (int j = 0; j < 4; j++) {
            const int k = lane + 32 * j;
            const uint4* up = reinterpret_cast<const uint4*>(us + k * 16);
            uint4 r0 = up[0], r1 = up[1];
            float u[16];
            {
                const __half2* h = reinterpret_cast<const __half2*>(&r0);
#pragma unroll
                for (int m = 0; m < 4; m++) { float2 f = __half22float2(h[m]); u[2*m]=f.x; u[2*m+1]=f.y; }
                h = reinterpret_cast<const __half2*>(&r1);
#pragma unroll
                for (int m = 0; m < 4; m++) { float2 f = __half22float2(h[m]); u[8+2*m]=f.x; u[8+2*m+1]=f.y; }
            }
            float s2 = 0.f, dot = 0.f;
            const float4* vp = reinterpret_cast<const float4*>(v_sm + k * 16);
#pragma unroll
            for (int m = 0; m < 4; m++) {
                float4 vv = vp[m];
                s2  += u[4*m+0]*u[4*m+0] + u[4*m+1]*u[4*m+1] + u[4*m+2]*u[4*m+2] + u[4*m+3]*u[4*m+3];
                dot += u[4*m+0]*vv.x + u[4*m+1]*vv.y + u[4*m+2]*vv.z + u[4*m+3]*vv.w;
            }
            float sc = sqrtf(s2) / (0.5f + s2);
            float dd = 1.f - (sc * sc * s2 - 2.f * sc * dot + vn_sm[k]);
            if (IT == 2) {
                lg[j] = dd;
                g_logits[((size_t)b * N_ + i) * K_ + k] = dd;
            } else {
                lg[j] = dd + g_logits[((size_t)b * N_ + i) * K_ + k];
            }
        }
        // softmax over all 128 k (4 per lane, warp reduce)
        float mx = fmaxf(fmaxf(lg[0], lg[1]), fmaxf(lg[2], lg[3]));
#pragma unroll
        for (int o = 16; o > 0; o >>= 1) mx = fmaxf(mx, __shfl_xor_sync(0xffffffffu, mx, o));
        float e0 = __expf(lg[0]-mx), e1 = __expf(lg[1]-mx), e2 = __expf(lg[2]-mx), e3 = __expf(lg[3]-mx);
        float ssum = e0 + e1 + e2 + e3;
#pragma unroll
        for (int o = 16; o > 0; o >>= 1) ssum += __shfl_xor_sync(0xffffffffu, ssum, o);
        const float invs = 1.f / ssum;
        float ee[4] = {e0, e1, e2, e3};
#pragma unroll
        for (int j = 0; j < 4; j++) {
            const int k = lane + 32 * j;
            const float c = ee[j] * invs;
            atomicAdd(&s_sm[k], c);
            const uint4* up = reinterpret_cast<const uint4*>(us + k * 16);
            uint4 r0 = up[0], r1 = up[1];
            const __half2* h0 = reinterpret_cast<const __half2*>(&r0);
            const __half2* h1 = reinterpret_cast<const __half2*>(&r1);
            float* tb = t_sm + k * 17;
#pragma unroll
            for (int m = 0; m < 4; m++) {
                float2 f = __half22float2(h0[m]);
                atomicAdd(&tb[2*m],   c * f.x);
                atomicAdd(&tb[2*m+1], c * f.y);
            }
#pragma unroll
            for (int m = 0; m < 4; m++) {
                float2 f = __half22float2(h1[m]);
                atomicAdd(&tb[8+2*m],   c * f.x);
                atomicAdd(&tb[8+2*m+1], c * f.y);
            }
        }
        __syncwarp();
    }
    __syncthreads();
    for (int e = tid; e < 2048; e += 256) {
        int k = e >> 4, d = e & 15;
        atomicAdd(&g_t[IT - 1][b * KD_ + e], t_sm[k * 17 + d]);
    }
    if (tid < 128) atomicAdd(&g_S[IT - 2][b * K_ + tid], s_sm[tid]);
}

// ---------------- final: poses + activations -> d_out ----------------
__global__ void k_final(float* __restrict__ out) {
    const int idx = blockIdx.x * 256 + threadIdx.x;  // b*K + k
    const float inv = 1.0f / g_S[1][idx];
    const float4* tp = reinterpret_cast<const float4*>(&g_t[2][0] + idx * 16);
    float w[16]; float s2 = 0.f;
#pragma unroll
    for (int q = 0; q < 4; q++) {
        float4 tv = tp[q];
        w[q*4+0]=tv.x*inv; w[q*4+1]=tv.y*inv; w[q*4+2]=tv.z*inv; w[q*4+3]=tv.w*inv;
        s2 += w[q*4+0]*w[q*4+0] + w[q*4+1]*w[q*4+1] + w[q*4+2]*w[q*4+2] + w[q*4+3]*w[q*4+3];
    }
    float sc = sqrtf(s2) / (0.5f + s2);
    float4* op = reinterpret_cast<float4*>(out + idx * 16);
#pragma unroll
    for (int q = 0; q < 4; q++) {
        float4 o; o.x=sc*w[q*4+0]; o.y=sc*w[q*4+1]; o.z=sc*w[q*4+2]; o.w=sc*w[q*4+3];
        op[q] = o;
    }
    out[B_ * KD_ + idx] = s2 / (0.5f + s2);  // ||v|| = scale*sqrt(s2)
}

// ---------------- launch ----------------
extern "C" void kernel_launch(void* const* d_in, const int* in_sizes, int n_in,
                              void* d_out, int out_size) {
    const float* x      = (const float*)d_in[0];
    const void*  labels = d_in[2];
    const float* W1     = (const float*)d_in[3];
    float*       out    = (float*)d_out;

    const int ROUTE_SMEM = (4480 * 4) + (8 * 2048 * 2);  // 50688 bytes
    cudaFuncSetAttribute((const void*)k_route<2>, cudaFuncAttributeMaxDynamicSharedMemorySize, ROUTE_SMEM);
    cudaFuncSetAttribute((const void*)k_route<3>, cudaFuncAttributeMaxDynamicSharedMemorySize, ROUTE_SMEM);

    k_init<<<768, 256>>>();
    k_pass1<<<dim3(128, 8), 256>>>(x, labels, W1);
    k_finalize<<<16, 256>>>(0);                 // v1 = squash(sum_i u / 2048)
    k_route<2><<<2048, 256, ROUTE_SMEM>>>();    // dd(v1) -> b1, accumulate t2,S2
    k_finalize<<<16, 256>>>(1);                 // v2 = squash(t2/S2)
    k_route<3><<<2048, 256, ROUTE_SMEM>>>();    // dd(v2) -> b2, accumulate t3,S3
    k_final<<<16, 256>>>(out);                  // poses + activations
    (void)in_sizes; (void)n_in; (void)out_size;
}

// round 3
// speedup vs baseline: 2.0747x; 2.0747x over previous
#include <cuda_runtime.h>
#include <cuda_fp16.h>
#include <cstdint>

#define B_  32
#define N_  2048
#define K_  128
#define CI_ 16
#define CO_ 16
#define KD_ (K_*CO_)   // 2048

typedef unsigned long long ull;

// XOR swizzle (SW128 style): permutes 16B cells within 1KB atoms -> conflict-free
#define SW(o) ((o) ^ (((o) >> 3) & 0x70))

// ---------------- scratch (device globals; no allocation allowed) ----------------
__device__ __half g_uhat[(size_t)B_ * N_ * KD_];   // [b][i][k][d]  fp16, 268MB
__device__ float  g_t[3][B_ * KD_];                // per-iter weighted sums  [b][k][d]
__device__ float  g_S[2][B_ * K_];                 // per-iter coupling sums  [b][k]
__device__ float  g_v[2][B_ * KD_];                // v after iter1 / iter2   [b][k][d]
__device__ float  g_vn[2][B_ * K_];                // ||v||^2                 [b][k]

// ---------------- f32x2 packed helpers (Blackwell) ----------------
__device__ __forceinline__ ull pack2(float a, float b) {
    ull r; asm("mov.b64 %0, {%1,%2};" : "=l"(r) : "f"(a), "f"(b)); return r;
}
__device__ __forceinline__ void unpack2(ull v, float& a, float& b) {
    asm("mov.b64 {%0,%1}, %2;" : "=f"(a), "=f"(b) : "l"(v));
}
__device__ __forceinline__ void ffma2(ull& d, ull a, ull b) {
    asm("fma.rn.f32x2 %0, %1, %2, %0;" : "+l"(d) : "l"(a), "l"(b));
}
__device__ __forceinline__ void fadd2(ull& d, ull a) {
    asm("add.rn.f32x2 %0, %0, %1;" : "+l"(d) : "l"(a));
}

// labels dtype-agnostic (int32 vs int64); labels = arange(128)
__device__ __forceinline__ int load_label(const void* labels, int k) {
    const int* p32 = (const int*)labels;
    if (p32[1] == 1) return p32[k];
    return (int)((const long long*)labels)[k];
}

// ---------------- init: zero accumulators ----------------
__global__ void k_init() {
    int idx = blockIdx.x * 256 + threadIdx.x;
    if (idx < 3 * B_ * KD_) (&g_t[0][0])[idx] = 0.f;
    if (idx < 2 * B_ * K_)  (&g_S[0][0])[idx] = 0.f;
}

// ---------------- pass 1: u_hat (fp32 compute, fp16 store) + t0 = sum_i u_hat ----
__global__ void __launch_bounds__(256) k_pass1(const float* __restrict__ x,
                                               const void* __restrict__ labels,
                                               const float* __restrict__ W1) {
    __shared__ __align__(16) float xs[512];     // packed x pairs: [(bp*16+c)*2 + h]
    const int tid = threadIdx.x;
    const int kd  = blockIdx.y * 256 + tid;     // 0..2047
    const int k   = kd >> 4;
    const int d   = kd & 15;
    int ksrc = load_label(labels, k);
    if ((unsigned)ksrc >= (unsigned)K_) ksrc = k;
    const int i0  = blockIdx.x * 16;

    ull tsum[16];
#pragma unroll
    for (int bp = 0; bp < 16; bp++) tsum[bp] = 0ull;

    for (int ii = 0; ii < 16; ii++) {
        const int i = i0 + ii;
        __syncthreads();
        for (int e = tid; e < 512; e += 256) {
            int b = e >> 4, c = e & 15;
            xs[((b >> 1) * 16 + c) * 2 + (b & 1)] = x[((size_t)b * N_ + i) * CI_ + c];
        }
        __syncthreads();

        const float4* wp = reinterpret_cast<const float4*>(
            W1 + (((size_t)i * K_ + ksrc) * CO_ + d) * CI_);
        float4 w0 = wp[0], w1 = wp[1], w2 = wp[2], w3 = wp[3];
        ull wd[16];
        wd[0]=pack2(w0.x,w0.x); wd[1]=pack2(w0.y,w0.y); wd[2]=pack2(w0.z,w0.z); wd[3]=pack2(w0.w,w0.w);
        wd[4]=pack2(w1.x,w1.x); wd[5]=pack2(w1.y,w1.y); wd[6]=pack2(w1.z,w1.z); wd[7]=pack2(w1.w,w1.w);
        wd[8]=pack2(w2.x,w2.x); wd[9]=pack2(w2.y,w2.y); wd[10]=pack2(w2.z,w2.z); wd[11]=pack2(w2.w,w2.w);
        wd[12]=pack2(w3.x,w3.x); wd[13]=pack2(w3.y,w3.y); wd[14]=pack2(w3.z,w3.z); wd[15]=pack2(w3.w,w3.w);

#pragma unroll
        for (int bp = 0; bp < 16; bp++) {
            const ull* xv = reinterpret_cast<const ull*>(xs) + bp * 16;
            ull acc = 0ull;
#pragma unroll
            for (int c = 0; c < 16; c++) ffma2(acc, wd[c], xv[c]);
            fadd2(tsum[bp], acc);
            float lo, hi; unpack2(acc, lo, hi);
            g_uhat[((size_t)(2 * bp)     * N_ + i) * KD_ + kd] = __float2half_rn(lo);
            g_uhat[((size_t)(2 * bp + 1) * N_ + i) * KD_ + kd] = __float2half_rn(hi);
        }
    }
#pragma unroll
    for (int bp = 0; bp < 16; bp++) {
        float a, bb; unpack2(tsum[bp], a, bb);
        atomicAdd(&g_t[0][(2 * bp)     * KD_ + kd], a);
        atomicAdd(&g_t[0][(2 * bp + 1) * KD_ + kd], bb);
    }
}

// ---------------- finalize: v[which] = squash(t * inv), vn[which] = ||v||^2 ------
__global__ void k_finalize(int which) {   // 0: t0/2048 -> v0 ; 1: t1/S0 -> v1
    const int idx = blockIdx.x * 256 + threadIdx.x;   // b*K + k
    const float* t = g_t[which];
    float inv = (which == 0) ? (1.0f / 2048.0f) : (1.0f / g_S[0][idx]);
    const float4* tp = reinterpret_cast<const float4*>(t + idx * 16);
    float w[16]; float s2 = 0.f;
#pragma unroll
    for (int q = 0; q < 4; q++) {
        float4 tv = tp[q];
        w[q*4+0]=tv.x*inv; w[q*4+1]=tv.y*inv; w[q*4+2]=tv.z*inv; w[q*4+3]=tv.w*inv;
        s2 += w[q*4+0]*w[q*4+0] + w[q*4+1]*w[q*4+1] + w[q*4+2]*w[q*4+2] + w[q*4+3]*w[q*4+3];
    }
    float sc = sqrtf(s2) / (0.5f + s2);
    float4* vp = reinterpret_cast<float4*>(g_v[which] + idx * 16);
#pragma unroll
    for (int q = 0; q < 4; q++) {
        float4 o; o.x=sc*w[q*4+0]; o.y=sc*w[q*4+1]; o.z=sc*w[q*4+2]; o.w=sc*w[q*4+3];
        vp[q] = o;
    }
    g_vn[which][idx] = sc * sc * s2;
}

// ---------------- routing pass (iteration 2 or 3): NO shared atomics ------------
// grid 2048 (32 b * 64 chunks of 32 i), block 256 (8 warps).
// Per 8-i group: phase A (warp owns i: dd -> softmax -> c_sm),
//                phase B (warp owns 16 k's: register-accumulate t,S over the 8 i).
template <int IT>
__global__ void __launch_bounds__(256) k_route() {
    extern __shared__ __align__(128) float sm[];
    float* v1  = sm;            // 2048 (swizzled 16B cells)
    float* vn1 = sm + 2048;     // 128
    float* cke = sm + 2176;     // 8 * 128
    float* v2  = sm + 3200;     // IT3 only: 2048 (swizzled)
    float* vn2 = sm + 5248;     // IT3 only: 128
    char*  ub  = (char*)(sm + (IT == 3 ? 5376 : 3200));  // 8 * 4KB u slices (swizzled)

    const int tid = threadIdx.x, lane = tid & 31, warp = tid >> 5;
    const int b   = blockIdx.x >> 6;
    const int ch  = blockIdx.x & 63;

    // cooperative v load with swizzled store (warp writes 1KB contiguous -> conflict-free)
    for (int e = tid; e < 2048; e += 256) {
        *(float*)((char*)v1 + SW(e * 4)) = g_v[0][b * KD_ + e];
        if (IT == 3) *(float*)((char*)v2 + SW(e * 4)) = g_v[1][b * KD_ + e];
    }
    if (tid < 128) {
        vn1[tid] = g_vn[0][b * K_ + tid];
        if (IT == 3) vn2[tid] = g_vn[1][b * K_ + tid];
    }
    __syncthreads();

    // phase-B ownership: lane -> (k, d-half)
    const int myk = warp * 16 + (lane >> 1);
    float tacc[8];
#pragma unroll
    for (int m = 0; m < 8; m++) tacc[m] = 0.f;
    float sacc = 0.f;

    char* myslice = ub + warp * 4096;

    for (int q = 0; q < 4; q++) {
        const int i = ch * 32 + q * 8 + warp;
        // ---- stage u_hat[b][i][:][:] (4KB contiguous) into swizzled SMEM slice ----
        const char* src = (const char*)(g_uhat + ((size_t)b * N_ + i) * KD_);
#pragma unroll
        for (int c = 0; c < 8; c++) {
            int off = (c * 32 + lane) * 16;
            *(uint4*)(myslice + SW(off)) = *(const uint4*)(src + off);
        }
        __syncwarp();

        // ---- phase A: dd logits for own i, softmax over k, write c to SMEM ----
        float lg[4];
#pragma unroll
        for (int j = 0; j < 4; j++) {
            const int k = lane + 32 * j;
            uint4 r0 = *(const uint4*)(myslice + SW(k * 32));
            uint4 r1 = *(const uint4*)(myslice + SW(k * 32 + 16));
            float u[16];
            {
                const __half2* h = reinterpret_cast<const __half2*>(&r0);
#pragma unroll
                for (int m = 0; m < 4; m++) { float2 f = __half22float2(h[m]); u[2*m]=f.x; u[2*m+1]=f.y; }
                h = reinterpret_cast<const __half2*>(&r1);
#pragma unroll
                for (int m = 0; m < 4; m++) { float2 f = __half22float2(h[m]); u[8+2*m]=f.x; u[8+2*m+1]=f.y; }
            }
            float s2 = 0.f, dot1 = 0.f, dot2 = 0.f;
#pragma unroll
            for (int m = 0; m < 4; m++) {
                float4 vv = *(const float4*)((char*)v1 + SW(k * 64 + m * 16));
                s2   += u[4*m+0]*u[4*m+0] + u[4*m+1]*u[4*m+1] + u[4*m+2]*u[4*m+2] + u[4*m+3]*u[4*m+3];
                dot1 += u[4*m+0]*vv.x + u[4*m+1]*vv.y + u[4*m+2]*vv.z + u[4*m+3]*vv.w;
                if (IT == 3) {
                    float4 w2 = *(const float4*)((char*)v2 + SW(k * 64 + m * 16));
                    dot2 += u[4*m+0]*w2.x + u[4*m+1]*w2.y + u[4*m+2]*w2.z + u[4*m+3]*w2.w;
                }
            }
            float sc = sqrtf(s2) / (0.5f + s2);
            float usq = sc * sc * s2;
            float dd = 1.f - (usq - 2.f * sc * dot1 + vn1[k]);
            if (IT == 3) dd += 1.f - (usq - 2.f * sc * dot2 + vn2[k]);
            lg[j] = dd;
        }
        float mx = fmaxf(fmaxf(lg[0], lg[1]), fmaxf(lg[2], lg[3]));
#pragma unroll
        for (int o = 16; o > 0; o >>= 1) mx = fmaxf(mx, __shfl_xor_sync(0xffffffffu, mx, o));
        float e0 = __expf(lg[0]-mx), e1 = __expf(lg[1]-mx), e2 = __expf(lg[2]-mx), e3 = __expf(lg[3]-mx);
        float ssum = e0 + e1 + e2 + e3;
#pragma unroll
        for (int o = 16; o > 0; o >>= 1) ssum += __shfl_xor_sync(0xffffffffu, ssum, o);
        const float invs = 1.f / ssum;
        cke[warp * 128 + lane +  0] = e0 * invs;
        cke[warp * 128 + lane + 32] = e1 * invs;
        cke[warp * 128 + lane + 64] = e2 * invs;
        cke[warp * 128 + lane + 96] = e3 * invs;

        __syncthreads();   // c + u visible to all warps

        // ---- phase B: register accumulation over this 8-i group ----
#pragma unroll
        for (int i8 = 0; i8 < 8; i8++) {
            float c = cke[i8 * 128 + myk];
            uint4 uv = *(const uint4*)(ub + i8 * 4096 + SW(warp * 512 + lane * 16));
            const __half2* h = reinterpret_cast<const __half2*>(&uv);
#pragma unroll
            for (int m = 0; m < 4; m++) {
                float2 f = __half22float2(h[m]);
                tacc[2*m]   = fmaf(c, f.x, tacc[2*m]);
                tacc[2*m+1] = fmaf(c, f.y, tacc[2*m+1]);
            }
            sacc += c;
        }
        __syncthreads();   // protect u/c before next q overwrites
    }

    // ---- flush accumulators to global (disjoint (k,d) per lane within warp) ----
    float* gt = g_t[IT - 1] + b * KD_ + myk * 16 + (lane & 1) * 8;
#pragma unroll
    for (int m = 0; m < 8; m++) atomicAdd(gt + m, tacc[m]);
    if ((lane & 1) == 0) atomicAdd(&g_S[IT - 2][b * K_ + myk], sacc);
}

// ---------------- final: poses + activations -> d_out ----------------
__global__ void k_final(float* __restrict__ out) {
    const int idx = blockIdx.x * 256 + threadIdx.x;  // b*K + k
    const float inv = 1.0f / g_S[1][idx];
    const float4* tp = reinterpret_cast<const float4*>(&g_t[2][0] + idx * 16);
    float w[16]; float s2 = 0.f;
#pragma unroll
    for (int q = 0; q < 4; q++) {
        float4 tv = tp[q];
        w[q*4+0]=tv.x*inv; w[q*4+1]=tv.y*inv; w[q*4+2]=tv.z*inv; w[q*4+3]=tv.w*inv;
        s2 += w[q*4+0]*w[q*4+0] + w[q*4+1]*w[q*4+1] + w[q*4+2]*w[q*4+2] + w[q*4+3]*w[q*4+3];
    }
    float sc = sqrtf(s2) / (0.5f + s2);
    float4* op = reinterpret_cast<float4*>(out + idx * 16);
#pragma unroll
    for (int q = 0; q < 4; q++) {
        float4 o; o.x=sc*w[q*4+0]; o.y=sc*w[q*4+1]; o.z=sc*w[q*4+2]; o.w=sc*w[q*4+3];
        op[q] = o;
    }
    out[B_ * KD_ + idx] = s2 / (0.5f + s2);  // ||v||
}

// ---------------- launch ----------------
extern "C" void kernel_launch(void* const* d_in, const int* in_sizes, int n_in,
                              void* d_out, int out_size) {
    const float* x      = (const float*)d_in[0];
    const void*  labels = d_in[2];
    const float* W1     = (const float*)d_in[3];
    float*       out    = (float*)d_out;

    const int SMEM2 = 3200 * 4 + 32768;   // 45568
    const int SMEM3 = 5376 * 4 + 32768;   // 54272
    cudaFuncSetAttribute((const void*)k_route<2>, cudaFuncAttributeMaxDynamicSharedMemorySize, SMEM2);
    cudaFuncSetAttribute((const void*)k_route<3>, cudaFuncAttributeMaxDynamicSharedMemorySize, SMEM3);

    k_init<<<768, 256>>>();
    k_pass1<<<dim3(128, 8), 256>>>(x, labels, W1);
    k_finalize<<<16, 256>>>(0);               // v0 = squash(sum_i u / 2048)
    k_route<2><<<2048, 256, SMEM2>>>();       // dd(v0) -> t1, S0
    k_finalize<<<16, 256>>>(1);               // v1 = squash(t1/S0)
    k_route<3><<<2048, 256, SMEM3>>>();       // dd(v0)+dd(v1) -> t2, S1
    k_final<<<16, 256>>>(out);                // poses + activations
    (void)in_sizes; (void)n_in; (void)out_size;
}

// round 4
// speedup vs baseline: 2.4667x; 1.1889x over previous
#include <cuda_runtime.h>
#include <cuda_fp16.h>
#include <cstdint>

#define B_  32
#define N_  2048
#define K_  128
#define CI_ 16
#define CO_ 16
#define KD_ (K_*CO_)   // 2048

typedef unsigned long long ull;

// XOR swizzle (SW128 style): permutes 16B cells within 1KB atoms -> conflict-free
#define SW(o) ((o) ^ (((o) >> 3) & 0x70))

// ---------------- scratch (device globals; no allocation allowed) ----------------
__device__ __half g_uhat[(size_t)B_ * N_ * KD_];   // [b][i][k][d]  fp16, 268MB
__device__ float  g_t[3][B_ * KD_];                // per-iter weighted sums  [b][k][d]
__device__ float  g_S[2][B_ * K_];                 // per-iter coupling sums  [b][k]
__device__ float  g_v[2][B_ * KD_];                // v after iter1 / iter2   [b][k][d]
__device__ float  g_vn[2][B_ * K_];                // ||v||^2                 [b][k]

// ---------------- f32x2 packed helpers (Blackwell) ----------------
__device__ __forceinline__ ull pack2(float a, float b) {
    ull r; asm("mov.b64 %0, {%1,%2};" : "=l"(r) : "f"(a), "f"(b)); return r;
}
__device__ __forceinline__ void unpack2(ull v, float& a, float& b) {
    asm("mov.b64 {%0,%1}, %2;" : "=f"(a), "=f"(b) : "l"(v));
}
__device__ __forceinline__ void ffma2(ull& d, ull a, ull b) {
    asm("fma.rn.f32x2 %0, %1, %2, %0;" : "+l"(d) : "l"(a), "l"(b));
}
__device__ __forceinline__ void fadd2(ull& d, ull a) {
    asm("add.rn.f32x2 %0, %0, %1;" : "+l"(d) : "l"(a));
}

// labels dtype-agnostic (int32 vs int64); labels = arange(128)
__device__ __forceinline__ int load_label(const void* labels, int k) {
    const int* p32 = (const int*)labels;
    if (p32[1] == 1) return p32[k];
    return (int)((const long long*)labels)[k];
}

// ---------------- init: zero accumulators ----------------
__global__ void k_init() {
    int idx = blockIdx.x * 256 + threadIdx.x;
    if (idx < 3 * B_ * KD_) (&g_t[0][0])[idx] = 0.f;
    if (idx < 2 * B_ * K_)  (&g_S[0][0])[idx] = 0.f;
}

// ---------------- pass 1: u_hat (fp32 compute, fp16 store) + t0 = sum_i u_hat ----
// grid (128, 8), block 256.  All 16 i's of x staged ONCE -> barrier-free mainloop.
// W double-buffered in registers to hide DRAM latency.
__global__ void __launch_bounds__(256, 2) k_pass1(const float* __restrict__ x,
                                                  const void* __restrict__ labels,
                                                  const float* __restrict__ W1) {
    __shared__ __align__(16) float xs[16 * 512];   // [i][(bp*16+c)*2 + (b&1)]
    const int tid = threadIdx.x;
    const int kd  = blockIdx.y * 256 + tid;        // 0..2047
    const int k   = kd >> 4;
    const int d   = kd & 15;
    int ksrc = load_label(labels, k);
    if ((unsigned)ksrc >= (unsigned)K_) ksrc = k;
    const int i0  = blockIdx.x * 16;

    // ---- stage x[:, i0:i0+16, :] pair-packed, single barrier ----
    for (int e = tid; e < 8192; e += 256) {
        const int b = e >> 8, rem = e & 255, i = rem >> 4, c = rem & 15;
        xs[i * 512 + ((b >> 1) * 16 + c) * 2 + (b & 1)] =
            x[((size_t)b * N_ + i0 + i) * CI_ + c];
    }
    __syncthreads();

    ull tsum[16];
#pragma unroll
    for (int bp = 0; bp < 16; bp++) tsum[bp] = 0ull;

    const size_t wstride4 = (size_t)K_ * CO_ * CI_ / 4;   // float4 per i
    const float4* wp = reinterpret_cast<const float4*>(
        W1 + (((size_t)i0 * K_ + ksrc) * CO_ + d) * CI_);

    float4 cw0 = wp[0], cw1 = wp[1], cw2 = wp[2], cw3 = wp[3];

    for (int ii = 0; ii < 16; ii++) {
        float4 nw0, nw1, nw2, nw3;
        if (ii < 15) {                       // prefetch next W tile
            const float4* np = wp + (size_t)(ii + 1) * wstride4;
            nw0 = np[0]; nw1 = np[1]; nw2 = np[2]; nw3 = np[3];
        }
        ull wd[16];
        wd[0]=pack2(cw0.x,cw0.x); wd[1]=pack2(cw0.y,cw0.y); wd[2]=pack2(cw0.z,cw0.z); wd[3]=pack2(cw0.w,cw0.w);
        wd[4]=pack2(cw1.x,cw1.x); wd[5]=pack2(cw1.y,cw1.y); wd[6]=pack2(cw1.z,cw1.z); wd[7]=pack2(cw1.w,cw1.w);
        wd[8]=pack2(cw2.x,cw2.x); wd[9]=pack2(cw2.y,cw2.y); wd[10]=pack2(cw2.z,cw2.z); wd[11]=pack2(cw2.w,cw2.w);
        wd[12]=pack2(cw3.x,cw3.x); wd[13]=pack2(cw3.y,cw3.y); wd[14]=pack2(cw3.z,cw3.z); wd[15]=pack2(cw3.w,cw3.w);

        const int i = i0 + ii;
        __half* ubase = g_uhat + (size_t)i * KD_ + kd;
#pragma unroll
        for (int bp = 0; bp < 16; bp++) {
            const ulonglong2* xq = reinterpret_cast<const ulonglong2*>(xs + ii * 512 + bp * 32);
            ulonglong2 p0 = xq[0], p1 = xq[1], p2 = xq[2], p3 = xq[3];
            ulonglong2 p4 = xq[4], p5 = xq[5], p6 = xq[6], p7 = xq[7];
            ull acc = 0ull;
            ffma2(acc, wd[0],  p0.x); ffma2(acc, wd[1],  p0.y);
            ffma2(acc, wd[2],  p1.x); ffma2(acc, wd[3],  p1.y);
            ffma2(acc, wd[4],  p2.x); ffma2(acc, wd[5],  p2.y);
            ffma2(acc, wd[6],  p3.x); ffma2(acc, wd[7],  p3.y);
            ffma2(acc, wd[8],  p4.x); ffma2(acc, wd[9],  p4.y);
            ffma2(acc, wd[10], p5.x); ffma2(acc, wd[11], p5.y);
            ffma2(acc, wd[12], p6.x); ffma2(acc, wd[13], p6.y);
            ffma2(acc, wd[14], p7.x); ffma2(acc, wd[15], p7.y);
            fadd2(tsum[bp], acc);
            float lo, hi; unpack2(acc, lo, hi);
            ubase[(size_t)(2 * bp)     * N_ * KD_] = __float2half_rn(lo);
            ubase[(size_t)(2 * bp + 1) * N_ * KD_] = __float2half_rn(hi);
        }
        cw0 = nw0; cw1 = nw1; cw2 = nw2; cw3 = nw3;
    }
#pragma unroll
    for (int bp = 0; bp < 16; bp++) {
        float a, bb; unpack2(tsum[bp], a, bb);
        atomicAdd(&g_t[0][(2 * bp)     * KD_ + kd], a);
        atomicAdd(&g_t[0][(2 * bp + 1) * KD_ + kd], bb);
    }
}

// ---------------- finalize: v[which] = squash(t * inv), vn[which] = ||v||^2 ------
__global__ void k_finalize(int which) {   // 0: t0/2048 -> v0 ; 1: t1/S0 -> v1
    const int idx = blockIdx.x * 256 + threadIdx.x;   // b*K + k
    const float* t = g_t[which];
    float inv = (which == 0) ? (1.0f / 2048.0f) : (1.0f / g_S[0][idx]);
    const float4* tp = reinterpret_cast<const float4*>(t + idx * 16);
    float w[16]; float s2 = 0.f;
#pragma unroll
    for (int q = 0; q < 4; q++) {
        float4 tv = tp[q];
        w[q*4+0]=tv.x*inv; w[q*4+1]=tv.y*inv; w[q*4+2]=tv.z*inv; w[q*4+3]=tv.w*inv;
        s2 += w[q*4+0]*w[q*4+0] + w[q*4+1]*w[q*4+1] + w[q*4+2]*w[q*4+2] + w[q*4+3]*w[q*4+3];
    }
    float sc = sqrtf(s2) / (0.5f + s2);
    float4* vp = reinterpret_cast<float4*>(g_v[which] + idx * 16);
#pragma unroll
    for (int q = 0; q < 4; q++) {
        float4 o; o.x=sc*w[q*4+0]; o.y=sc*w[q*4+1]; o.z=sc*w[q*4+2]; o.w=sc*w[q*4+3];
        vp[q] = o;
    }
    g_vn[which][idx] = sc * sc * s2;
}

// ---------------- routing pass (iteration 2 or 3): NO shared atomics ------------
template <int IT>
__global__ void __launch_bounds__(256) k_route() {
    extern __shared__ __align__(128) float sm[];
    float* v1  = sm;            // 2048 (swizzled 16B cells)
    float* vn1 = sm + 2048;     // 128
    float* cke = sm + 2176;     // 8 * 128
    float* v2  = sm + 3200;     // IT3 only: 2048 (swizzled)
    float* vn2 = sm + 5248;     // IT3 only: 128
    char*  ub  = (char*)(sm + (IT == 3 ? 5376 : 3200));  // 8 * 4KB u slices (swizzled)

    const int tid = threadIdx.x, lane = tid & 31, warp = tid >> 5;
    const int b   = blockIdx.x >> 6;
    const int ch  = blockIdx.x & 63;

    for (int e = tid; e < 2048; e += 256) {
        *(float*)((char*)v1 + SW(e * 4)) = g_v[0][b * KD_ + e];
        if (IT == 3) *(float*)((char*)v2 + SW(e * 4)) = g_v[1][b * KD_ + e];
    }
    if (tid < 128) {
        vn1[tid] = g_vn[0][b * K_ + tid];
        if (IT == 3) vn2[tid] = g_vn[1][b * K_ + tid];
    }
    __syncthreads();

    const int myk = warp * 16 + (lane >> 1);
    float tacc[8];
#pragma unroll
    for (int m = 0; m < 8; m++) tacc[m] = 0.f;
    float sacc = 0.f;

    char* myslice = ub + warp * 4096;

    for (int q = 0; q < 4; q++) {
        const int i = ch * 32 + q * 8 + warp;
        const char* src = (const char*)(g_uhat + ((size_t)b * N_ + i) * KD_);
#pragma unroll
        for (int c = 0; c < 8; c++) {
            int off = (c * 32 + lane) * 16;
            *(uint4*)(myslice + SW(off)) = *(const uint4*)(src + off);
        }
        __syncwarp();

        float lg[4];
#pragma unroll
        for (int j = 0; j < 4; j++) {
            const int k = lane + 32 * j;
            uint4 r0 = *(const uint4*)(myslice + SW(k * 32));
            uint4 r1 = *(const uint4*)(myslice + SW(k * 32 + 16));
            float u[16];
            {
                const __half2* h = reinterpret_cast<const __half2*>(&r0);
#pragma unroll
                for (int m = 0; m < 4; m++) { float2 f = __half22float2(h[m]); u[2*m]=f.x; u[2*m+1]=f.y; }
                h = reinterpret_cast<const __half2*>(&r1);
#pragma unroll
                for (int m = 0; m < 4; m++) { float2 f = __half22float2(h[m]); u[8+2*m]=f.x; u[8+2*m+1]=f.y; }
            }
            float s2 = 0.f, dot1 = 0.f, dot2 = 0.f;
#pragma unroll
            for (int m = 0; m < 4; m++) {
                float4 vv = *(const float4*)((char*)v1 + SW(k * 64 + m * 16));
                s2   += u[4*m+0]*u[4*m+0] + u[4*m+1]*u[4*m+1] + u[4*m+2]*u[4*m+2] + u[4*m+3]*u[4*m+3];
                dot1 += u[4*m+0]*vv.x + u[4*m+1]*vv.y + u[4*m+2]*vv.z + u[4*m+3]*vv.w;
                if (IT == 3) {
                    float4 w2 = *(const float4*)((char*)v2 + SW(k * 64 + m * 16));
                    dot2 += u[4*m+0]*w2.x + u[4*m+1]*w2.y + u[4*m+2]*w2.z + u[4*m+3]*w2.w;
                }
            }
            float sc = sqrtf(s2) / (0.5f + s2);
            float usq = sc * sc * s2;
            float dd = 1.f - (usq - 2.f * sc * dot1 + vn1[k]);
            if (IT == 3) dd += 1.f - (usq - 2.f * sc * dot2 + vn2[k]);
            lg[j] = dd;
        }
        float mx = fmaxf(fmaxf(lg[0], lg[1]), fmaxf(lg[2], lg[3]));
#pragma unroll
        for (int o = 16; o > 0; o >>= 1) mx = fmaxf(mx, __shfl_xor_sync(0xffffffffu, mx, o));
        float e0 = __expf(lg[0]-mx), e1 = __expf(lg[1]-mx), e2 = __expf(lg[2]-mx), e3 = __expf(lg[3]-mx);
        float ssum = e0 + e1 + e2 + e3;
#pragma unroll
        for (int o = 16; o > 0; o >>= 1) ssum += __shfl_xor_sync(0xffffffffu, ssum, o);
        const float invs = 1.f / ssum;
        cke[warp * 128 + lane +  0] = e0 * invs;
        cke[warp * 128 + lane + 32] = e1 * invs;
        cke[warp * 128 + lane + 64] = e2 * invs;
        cke[warp * 128 + lane + 96] = e3 * invs;

        __syncthreads();

#pragma unroll
        for (int i8 = 0; i8 < 8; i8++) {
            float c = cke[i8 * 128 + myk];
            uint4 uv = *(const uint4*)(ub + i8 * 4096 + SW(warp * 512 + lane * 16));
            const __half2* h = reinterpret_cast<const __half2*>(&uv);
#pragma unroll
            for (int m = 0; m < 4; m++) {
                float2 f = __half22float2(h[m]);
                tacc[2*m]   = fmaf(c, f.x, tacc[2*m]);
                tacc[2*m+1] = fmaf(c, f.y, tacc[2*m+1]);
            }
            sacc += c;
        }
        __syncthreads();
    }

    float* gt = g_t[IT - 1] + b * KD_ + myk * 16 + (lane & 1) * 8;
#pragma unroll
    for (int m = 0; m < 8; m++) atomicAdd(gt + m, tacc[m]);
    if ((lane & 1) == 0) atomicAdd(&g_S[IT - 2][b * K_ + myk], sacc);
}

// ---------------- final: poses + activations -> d_out ----------------
__global__ void k_final(float* __restrict__ out) {
    const int idx = blockIdx.x * 256 + threadIdx.x;  // b*K + k
    const float inv = 1.0f / g_S[1][idx];
    const float4* tp = reinterpret_cast<const float4*>(&g_t[2][0] + idx * 16);
    float w[16]; float s2 = 0.f;
#pragma unroll
    for (int q = 0; q < 4; q++) {
        float4 tv = tp[q];
        w[q*4+0]=tv.x*inv; w[q*4+1]=tv.y*inv; w[q*4+2]=tv.z*inv; w[q*4+3]=tv.w*inv;
        s2 += w[q*4+0]*w[q*4+0] + w[q*4+1]*w[q*4+1] + w[q*4+2]*w[q*4+2] + w[q*4+3]*w[q*4+3];
    }
    float sc = sqrtf(s2) / (0.5f + s2);
    float4* op = reinterpret_cast<float4*>(out + idx * 16);
#pragma unroll
    for (int q = 0; q < 4; q++) {
        float4 o; o.x=sc*w[q*4+0]; o.y=sc*w[q*4+1]; o.z=sc*w[q*4+2]; o.w=sc*w[q*4+3];
        op[q] = o;
    }
    out[B_ * KD_ + idx] = s2 / (0.5f + s2);  // ||v||
}

// ---------------- launch ----------------
extern "C" void kernel_launch(void* const* d_in, const int* in_sizes, int n_in,
                              void* d_out, int out_size) {
    const float* x      = (const float*)d_in[0];
    const void*  labels = d_in[2];
    const float* W1     = (const float*)d_in[3];
    float*       out    = (float*)d_out;

    const int SMEM2 = 3200 * 4 + 32768;   // 45568
    const int SMEM3 = 5376 * 4 + 32768;   // 54272
    cudaFuncSetAttribute((const void*)k_route<2>, cudaFuncAttributeMaxDynamicSharedMemorySize, SMEM2);
    cudaFuncSetAttribute((const void*)k_route<3>, cudaFuncAttributeMaxDynamicSharedMemorySize, SMEM3);

    k_init<<<768, 256>>>();
    k_pass1<<<dim3(128, 8), 256>>>(x, labels, W1);
    k_finalize<<<16, 256>>>(0);               // v0 = squash(sum_i u / 2048)
    k_route<2><<<2048, 256, SMEM2>>>();       // dd(v0) -> t1, S0
    k_finalize<<<16, 256>>>(1);               // v1 = squash(t1/S0)
    k_route<3><<<2048, 256, SMEM3>>>();       // dd(v0)+dd(v1) -> t2, S1
    k_final<<<16, 256>>>(out);                // poses + activations
    (void)in_sizes; (void)n_in; (void)out_size;
}

// round 5
// speedup vs baseline: 2.5016x; 1.0141x over previous
#include <cuda_runtime.h>
#include <cuda_fp16.h>
#include <cstdint>

#define B_  32
#define N_  2048
#define K_  128
#define CI_ 16
#define CO_ 16
#define KD_ (K_*CO_)   // 2048

typedef unsigned long long ull;

// XOR swizzle (SW128 style): permutes 16B cells within 1KB atoms -> conflict-free
#define SW(o) ((o) ^ (((o) >> 3) & 0x70))

// cp.async helpers (Ampere+ LDGSTS)
#define CP_ASYNC16(saddr, gptr) \
    asm volatile("cp.async.cg.shared.global [%0], [%1], 16;" :: "r"(saddr), "l"(gptr))
#define CP_COMMIT() asm volatile("cp.async.commit_group;")
#define CP_WAIT0()  asm volatile("cp.async.wait_group 0;" ::: "memory")

// ---------------- scratch (device globals; no allocation allowed) ----------------
__device__ __half g_uhat[(size_t)B_ * N_ * KD_];   // [b][i][k][d]  fp16, 268MB
__device__ float  g_t[3][B_ * KD_];                // per-iter weighted sums  [b][k][d]
__device__ float  g_S[2][B_ * K_];                 // per-iter coupling sums  [b][k]
__device__ float  g_v[2][B_ * KD_];                // v after iter1 / iter2   [b][k][d]
__device__ float  g_vn[2][B_ * K_];                // ||v||^2                 [b][k]

// ---------------- f32x2 packed helpers (Blackwell) ----------------
__device__ __forceinline__ ull pack2(float a, float b) {
    ull r; asm("mov.b64 %0, {%1,%2};" : "=l"(r) : "f"(a), "f"(b)); return r;
}
__device__ __forceinline__ void unpack2(ull v, float& a, float& b) {
    asm("mov.b64 {%0,%1}, %2;" : "=f"(a), "=f"(b) : "l"(v));
}
__device__ __forceinline__ void ffma2(ull& d, ull a, ull b) {
    asm("fma.rn.f32x2 %0, %1, %2, %0;" : "+l"(d) : "l"(a), "l"(b));
}
__device__ __forceinline__ void fadd2(ull& d, ull a) {
    asm("add.rn.f32x2 %0, %0, %1;" : "+l"(d) : "l"(a));
}

// labels dtype-agnostic (int32 vs int64); labels = arange(128)
__device__ __forceinline__ int load_label(const void* labels, int k) {
    const int* p32 = (const int*)labels;
    if (p32[1] == 1) return p32[k];
    return (int)((const long long*)labels)[k];
}

// ---------------- init: zero accumulators ----------------
__global__ void k_init() {
    int idx = blockIdx.x * 256 + threadIdx.x;
    if (idx < 3 * B_ * KD_) (&g_t[0][0])[idx] = 0.f;
    if (idx < 2 * B_ * K_)  (&g_S[0][0])[idx] = 0.f;
}

// ---------------- pass 1: u_hat (fp32 compute, fp16 store) + t0 = sum_i u_hat ----
// grid (128, 8), block 256. Single x-staging barrier; W prefetched DEPTH-2 so each
// warp keeps 8 LDG.128 in flight (MLP-bound fix).
__global__ void __launch_bounds__(256, 2) k_pass1(const float* __restrict__ x,
                                                  const void* __restrict__ labels,
                                                  const float* __restrict__ W1) {
    __shared__ __align__(16) float xs[16 * 512];   // [i][(bp*16+c)*2 + (b&1)]
    const int tid = threadIdx.x;
    const int kd  = blockIdx.y * 256 + tid;        // 0..2047
    const int k   = kd >> 4;
    const int d   = kd & 15;
    int ksrc = load_label(labels, k);
    if ((unsigned)ksrc >= (unsigned)K_) ksrc = k;
    const int i0  = blockIdx.x * 16;

    // ---- stage x[:, i0:i0+16, :] pair-packed, single barrier ----
    for (int e = tid; e < 8192; e += 256) {
        const int b = e >> 8, rem = e & 255, i = rem >> 4, c = rem & 15;
        xs[i * 512 + ((b >> 1) * 16 + c) * 2 + (b & 1)] =
            x[((size_t)b * N_ + i0 + i) * CI_ + c];
    }
    __syncthreads();

    ull tsum[16];
#pragma unroll
    for (int bp = 0; bp < 16; bp++) tsum[bp] = 0ull;

    const size_t wstride4 = (size_t)K_ * CO_ * CI_ / 4;   // float4 per i
    const float4* wp = reinterpret_cast<const float4*>(
        W1 + (((size_t)i0 * K_ + ksrc) * CO_ + d) * CI_);

    // depth-2 register pipeline on W
    float4 cw0 = wp[0], cw1 = wp[1], cw2 = wp[2], cw3 = wp[3];
    const float4* np1 = wp + wstride4;
    float4 nw0 = np1[0], nw1 = np1[1], nw2 = np1[2], nw3 = np1[3];

    for (int ii = 0; ii < 16; ii++) {
        float4 mw0, mw1, mw2, mw3;
        if (ii < 14) {                        // prefetch ii+2
            const float4* np = wp + (size_t)(ii + 2) * wstride4;
            mw0 = np[0]; mw1 = np[1]; mw2 = np[2]; mw3 = np[3];
        }
        ull wd[16];
        wd[0]=pack2(cw0.x,cw0.x); wd[1]=pack2(cw0.y,cw0.y); wd[2]=pack2(cw0.z,cw0.z); wd[3]=pack2(cw0.w,cw0.w);
        wd[4]=pack2(cw1.x,cw1.x); wd[5]=pack2(cw1.y,cw1.y); wd[6]=pack2(cw1.z,cw1.z); wd[7]=pack2(cw1.w,cw1.w);
        wd[8]=pack2(cw2.x,cw2.x); wd[9]=pack2(cw2.y,cw2.y); wd[10]=pack2(cw2.z,cw2.z); wd[11]=pack2(cw2.w,cw2.w);
        wd[12]=pack2(cw3.x,cw3.x); wd[13]=pack2(cw3.y,cw3.y); wd[14]=pack2(cw3.z,cw3.z); wd[15]=pack2(cw3.w,cw3.w);

        const int i = i0 + ii;
        __half* ubase = g_uhat + (size_t)i * KD_ + kd;
#pragma unroll
        for (int bp = 0; bp < 16; bp++) {
            const ulonglong2* xq = reinterpret_cast<const ulonglong2*>(xs + ii * 512 + bp * 32);
            ulonglong2 p0 = xq[0], p1 = xq[1], p2 = xq[2], p3 = xq[3];
            ulonglong2 p4 = xq[4], p5 = xq[5], p6 = xq[6], p7 = xq[7];
            ull acc = 0ull;
            ffma2(acc, wd[0],  p0.x); ffma2(acc, wd[1],  p0.y);
            ffma2(acc, wd[2],  p1.x); ffma2(acc, wd[3],  p1.y);
            ffma2(acc, wd[4],  p2.x); ffma2(acc, wd[5],  p2.y);
            ffma2(acc, wd[6],  p3.x); ffma2(acc, wd[7],  p3.y);
            ffma2(acc, wd[8],  p4.x); ffma2(acc, wd[9],  p4.y);
            ffma2(acc, wd[10], p5.x); ffma2(acc, wd[11], p5.y);
            ffma2(acc, wd[12], p6.x); ffma2(acc, wd[13], p6.y);
            ffma2(acc, wd[14], p7.x); ffma2(acc, wd[15], p7.y);
            fadd2(tsum[bp], acc);
            float lo, hi; unpack2(acc, lo, hi);
            ubase[(size_t)(2 * bp)     * N_ * KD_] = __float2half_rn(lo);
            ubase[(size_t)(2 * bp + 1) * N_ * KD_] = __float2half_rn(hi);
        }
        cw0 = nw0; cw1 = nw1; cw2 = nw2; cw3 = nw3;
        nw0 = mw0; nw1 = mw1; nw2 = mw2; nw3 = mw3;
    }
#pragma unroll
    for (int bp = 0; bp < 16; bp++) {
        float a, bb; unpack2(tsum[bp], a, bb);
        atomicAdd(&g_t[0][(2 * bp)     * KD_ + kd], a);
        atomicAdd(&g_t[0][(2 * bp + 1) * KD_ + kd], bb);
    }
}

// ---------------- finalize: v[which] = squash(t * inv), vn[which] = ||v||^2 ------
__global__ void k_finalize(int which) {   // 0: t0/2048 -> v0 ; 1: t1/S0 -> v1
    const int idx = blockIdx.x * 256 + threadIdx.x;   // b*K + k
    const float* t = g_t[which];
    float inv = (which == 0) ? (1.0f / 2048.0f) : (1.0f / g_S[0][idx]);
    const float4* tp = reinterpret_cast<const float4*>(t + idx * 16);
    float w[16]; float s2 = 0.f;
#pragma unroll
    for (int q = 0; q < 4; q++) {
        float4 tv = tp[q];
        w[q*4+0]=tv.x*inv; w[q*4+1]=tv.y*inv; w[q*4+2]=tv.z*inv; w[q*4+3]=tv.w*inv;
        s2 += w[q*4+0]*w[q*4+0] + w[q*4+1]*w[q*4+1] + w[q*4+2]*w[q*4+2] + w[q*4+3]*w[q*4+3];
    }
    float sc = sqrtf(s2) / (0.5f + s2);
    float4* vp = reinterpret_cast<float4*>(g_v[which] + idx * 16);
#pragma unroll
    for (int q = 0; q < 4; q++) {
        float4 o; o.x=sc*w[q*4+0]; o.y=sc*w[q*4+1]; o.z=sc*w[q*4+2]; o.w=sc*w[q*4+3];
        vp[q] = o;
    }
    g_vn[which][idx] = sc * sc * s2;
}

// ---------------- routing pass (iteration 2 or 3) ------------------------------
// cp.async DOUBLE-BUFFERED u staging: next q's 32KB lands while phase A/B compute.
template <int IT>
__global__ void __launch_bounds__(256) k_route() {
    extern __shared__ __align__(128) float sm[];
    float* v1  = sm;            // 2048 (swizzled 16B cells)
    float* vn1 = sm + 2048;     // 128
    float* cke = sm + 2176;     // 8 * 128
    float* v2  = sm + 3200;     // IT3 only: 2048 (swizzled)
    float* vn2 = sm + 5248;     // IT3 only: 128
    char*  ub  = (char*)(sm + (IT == 3 ? 5376 : 3200));  // 2 x (8 x 4KB) u slices

    const int tid = threadIdx.x, lane = tid & 31, warp = tid >> 5;
    const int b   = blockIdx.x >> 6;
    const int ch  = blockIdx.x & 63;

    for (int e = tid; e < 2048; e += 256) {
        *(float*)((char*)v1 + SW(e * 4)) = g_v[0][b * KD_ + e];
        if (IT == 3) *(float*)((char*)v2 + SW(e * 4)) = g_v[1][b * KD_ + e];
    }
    if (tid < 128) {
        vn1[tid] = g_vn[0][b * K_ + tid];
        if (IT == 3) vn2[tid] = g_vn[1][b * K_ + tid];
    }

    const uint32_t ub_s = (uint32_t)__cvta_generic_to_shared(ub);

    // ---- issue q=0 staging into buffer 0 ----
    {
        const char* src = (const char*)(g_uhat + ((size_t)b * N_ + ch * 32 + warp) * KD_);
        uint32_t dst = ub_s + warp * 4096;
#pragma unroll
        for (int c = 0; c < 8; c++) {
            int off = (c * 32 + lane) * 16;
            CP_ASYNC16(dst + SW(off), src + off);
        }
        CP_COMMIT();
    }

    const int myk = warp * 16 + (lane >> 1);
    float tacc[8];
#pragma unroll
    for (int m = 0; m < 8; m++) tacc[m] = 0.f;
    float sacc = 0.f;

    int cur = 0;
    for (int q = 0; q < 4; q++) {
        CP_WAIT0();         // my slice for q has landed
        __syncthreads();    // all slices for q visible; all readers of other buf done

        // ---- prefetch q+1 into the other buffer (overlaps phase A+B) ----
        if (q < 3) {
            const int inext = ch * 32 + (q + 1) * 8 + warp;
            const char* src = (const char*)(g_uhat + ((size_t)b * N_ + inext) * KD_);
            uint32_t dst = ub_s + (cur ^ 1) * 32768 + warp * 4096;
#pragma unroll
            for (int c = 0; c < 8; c++) {
                int off = (c * 32 + lane) * 16;
                CP_ASYNC16(dst + SW(off), src + off);
            }
            CP_COMMIT();
        }

        char* myslice = ub + cur * 32768 + warp * 4096;

        // ---- phase A: dd logits for own i, softmax over k, write c to SMEM ----
        float lg[4];
#pragma unroll
        for (int j = 0; j < 4; j++) {
            const int k = lane + 32 * j;
            uint4 r0 = *(const uint4*)(myslice + SW(k * 32));
            uint4 r1 = *(const uint4*)(myslice + SW(k * 32 + 16));
            float u[16];
            {
                const __half2* h = reinterpret_cast<const __half2*>(&r0);
#pragma unroll
                for (int m = 0; m < 4; m++) { float2 f = __half22float2(h[m]); u[2*m]=f.x; u[2*m+1]=f.y; }
                h = reinterpret_cast<const __half2*>(&r1);
#pragma unroll
                for (int m = 0; m < 4; m++) { float2 f = __half22float2(h[m]); u[8+2*m]=f.x; u[8+2*m+1]=f.y; }
            }
            float s2 = 0.f, dot1 = 0.f, dot2 = 0.f;
#pragma unroll
            for (int m = 0; m < 4; m++) {
                float4 vv = *(const float4*)((char*)v1 + SW(k * 64 + m * 16));
                s2   += u[4*m+0]*u[4*m+0] + u[4*m+1]*u[4*m+1] + u[4*m+2]*u[4*m+2] + u[4*m+3]*u[4*m+3];
                dot1 += u[4*m+0]*vv.x + u[4*m+1]*vv.y + u[4*m+2]*vv.z + u[4*m+3]*vv.w;
                if (IT == 3) {
                    float4 w2 = *(const float4*)((char*)v2 + SW(k * 64 + m * 16));
                    dot2 += u[4*m+0]*w2.x + u[4*m+1]*w2.y + u[4*m+2]*w2.z + u[4*m+3]*w2.w;
                }
            }
            float sc = sqrtf(s2) / (0.5f + s2);
            float usq = sc * sc * s2;
            float dd = 1.f - (usq - 2.f * sc * dot1 + vn1[k]);
            if (IT == 3) dd += 1.f - (usq - 2.f * sc * dot2 + vn2[k]);
            lg[j] = dd;
        }
        float mx = fmaxf(fmaxf(lg[0], lg[1]), fmaxf(lg[2], lg[3]));
#pragma unroll
        for (int o = 16; o > 0; o >>= 1) mx = fmaxf(mx, __shfl_xor_sync(0xffffffffu, mx, o));
        float e0 = __expf(lg[0]-mx), e1 = __expf(lg[1]-mx), e2 = __expf(lg[2]-mx), e3 = __expf(lg[3]-mx);
        float ssum = e0 + e1 + e2 + e3;
#pragma unroll
        for (int o = 16; o > 0; o >>= 1) ssum += __shfl_xor_sync(0xffffffffu, ssum, o);
        const float invs = 1.f / ssum;
        cke[warp * 128 + lane +  0] = e0 * invs;
        cke[warp * 128 + lane + 32] = e1 * invs;
        cke[warp * 128 + lane + 64] = e2 * invs;
        cke[warp * 128 + lane + 96] = e3 * invs;

        __syncthreads();   // c + all slices ready for phase B

        // ---- phase B: register accumulation over this 8-i group ----
        char* bbase = ub + cur * 32768;
#pragma unroll
        for (int i8 = 0; i8 < 8; i8++) {
            float c = cke[i8 * 128 + myk];
            uint4 uv = *(const uint4*)(bbase + i8 * 4096 + SW(warp * 512 + lane * 16));
            const __half2* h = reinterpret_cast<const __half2*>(&uv);
#pragma unroll
            for (int m = 0; m < 4; m++) {
                float2 f = __half22float2(h[m]);
                tacc[2*m]   = fmaf(c, f.x, tacc[2*m]);
                tacc[2*m+1] = fmaf(c, f.y, tacc[2*m+1]);
            }
            sacc += c;
        }
        cur ^= 1;
    }

    float* gt = g_t[IT - 1] + b * KD_ + myk * 16 + (lane & 1) * 8;
#pragma unroll
    for (int m = 0; m < 8; m++) atomicAdd(gt + m, tacc[m]);
    if ((lane & 1) == 0) atomicAdd(&g_S[IT - 2][b * K_ + myk], sacc);
}

// ---------------- final: poses + activations -> d_out ----------------
__global__ void k_final(float* __restrict__ out) {
    const int idx = blockIdx.x * 256 + threadIdx.x;  // b*K + k
    const float inv = 1.0f / g_S[1][idx];
    const float4* tp = reinterpret_cast<const float4*>(&g_t[2][0] + idx * 16);
    float w[16]; float s2 = 0.f;
#pragma unroll
    for (int q = 0; q < 4; q++) {
        float4 tv = tp[q];
        w[q*4+0]=tv.x*inv; w[q*4+1]=tv.y*inv; w[q*4+2]=tv.z*inv; w[q*4+3]=tv.w*inv;
        s2 += w[q*4+0]*w[q*4+0] + w[q*4+1]*w[q*4+1] + w[q*4+2]*w[q*4+2] + w[q*4+3]*w[q*4+3];
    }
    float sc = sqrtf(s2) / (0.5f + s2);
    float4* op = reinterpret_cast<float4*>(out + idx * 16);
#pragma unroll
    for (int q = 0; q < 4; q++) {
        float4 o; o.x=sc*w[q*4+0]; o.y=sc*w[q*4+1]; o.z=sc*w[q*4+2]; o.w=sc*w[q*4+3];
        op[q] = o;
    }
    out[B_ * KD_ + idx] = s2 / (0.5f + s2);  // ||v||
}

// ---------------- launch ----------------
extern "C" void kernel_launch(void* const* d_in, const int* in_sizes, int n_in,
                              void* d_out, int out_size) {
    const float* x      = (const float*)d_in[0];
    const void*  labels = d_in[2];
    const float* W1     = (const float*)d_in[3];
    float*       out    = (float*)d_out;

    const int SMEM2 = 3200 * 4 + 2 * 32768;   // 78336
    const int SMEM3 = 5376 * 4 + 2 * 32768;   // 87040
    cudaFuncSetAttribute((const void*)k_route<2>, cudaFuncAttributeMaxDynamicSharedMemorySize, SMEM2);
    cudaFuncSetAttribute((const void*)k_route<3>, cudaFuncAttributeMaxDynamicSharedMemorySize, SMEM3);

    k_init<<<768, 256>>>();
    k_pass1<<<dim3(128, 8), 256>>>(x, labels, W1);
    k_finalize<<<16, 256>>>(0);               // v0 = squash(sum_i u / 2048)
    k_route<2><<<2048, 256, SMEM2>>>();       // dd(v0) -> t1, S0
    k_finalize<<<16, 256>>>(1);               // v1 = squash(t1/S0)
    k_route<3><<<2048, 256, SMEM3>>>();       // dd(v0)+dd(v1) -> t2, S1
    k_final<<<16, 256>>>(out);                // poses + activations
    (void)in_sizes; (void)n_in; (void)out_size;
}

// round 6
// speedup vs baseline: 2.7387x; 1.0948x over previous
#include <cuda_runtime.h>
#include <cuda_fp16.h>
#include <cstdint>

#define B_  32
#define N_  2048
#define K_  128
#define CI_ 16
#define CO_ 16
#define KD_ (K_*CO_)   // 2048

typedef unsigned long long ull;

// XOR swizzle (SW128 style): permutes 16B cells within 1KB atoms -> conflict-free
#define SW(o) ((o) ^ (((o) >> 3) & 0x70))

// cp.async helpers
#define CP_ASYNC16(saddr, gptr) \
    asm volatile("cp.async.cg.shared.global [%0], [%1], 16;" :: "r"(saddr), "l"(gptr))
#define CP_COMMIT() asm volatile("cp.async.commit_group;")
#define CP_WAIT0()  asm volatile("cp.async.wait_group 0;" ::: "memory")

// ---------------- scratch (device globals; no allocation allowed) ----------------
__device__ __half g_uhat[(size_t)B_ * N_ * KD_];   // [b][i][k][d]  fp16, 268MB
__device__ float  g_t[3][B_ * KD_];                // per-iter weighted sums  [b][k][d]
__device__ float  g_S[2][B_ * K_];                 // per-iter coupling sums  [b][k]
__device__ float  g_v[2][B_ * KD_];                // v after iter1 / iter2   [b][k][d]
__device__ float  g_vn[2][B_ * K_];                // ||v||^2                 [b][k]

// ---------------- f32x2 packed helpers ----------------
__device__ __forceinline__ ull pack2(float a, float b) {
    ull r; asm("mov.b64 %0, {%1,%2};" : "=l"(r) : "f"(a), "f"(b)); return r;
}
__device__ __forceinline__ void unpack2(ull v, float& a, float& b) {
    asm("mov.b64 {%0,%1}, %2;" : "=f"(a), "=f"(b) : "l"(v));
}
__device__ __forceinline__ void ffma2(ull& d, ull a, ull b) {
    asm("fma.rn.f32x2 %0, %1, %2, %0;" : "+l"(d) : "l"(a), "l"(b));
}
__device__ __forceinline__ void fadd2(ull& d, ull a) {
    asm("add.rn.f32x2 %0, %0, %1;" : "+l"(d) : "l"(a));
}

// labels dtype-agnostic (int32 vs int64); labels = arange(128)
__device__ __forceinline__ int load_label(const void* labels, int k) {
    const int* p32 = (const int*)labels;
    if (p32[1] == 1) return p32[k];
    return (int)((const long long*)labels)[k];
}

// ---------------- init: zero accumulators ----------------
__global__ void k_init() {
    int idx = blockIdx.x * 256 + threadIdx.x;
    if (idx < 3 * B_ * KD_) (&g_t[0][0])[idx] = 0.f;
    if (idx < 2 * B_ * K_)  (&g_S[0][0])[idx] = 0.f;
}

// ---------------- pass 1: u_hat (fp32 compute, fp16 store) + t0 = sum_i u_hat ----
__global__ void __launch_bounds__(256, 2) k_pass1(const float* __restrict__ x,
                                                  const void* __restrict__ labels,
                                                  const float* __restrict__ W1) {
    __shared__ __align__(16) float xs[16 * 512];   // [i][(bp*16+c)*2 + (b&1)]
    const int tid = threadIdx.x;
    const int kd  = blockIdx.y * 256 + tid;        // 0..2047
    const int k   = kd >> 4;
    const int d   = kd & 15;
    int ksrc = load_label(labels, k);
    if ((unsigned)ksrc >= (unsigned)K_) ksrc = k;
    const int i0  = blockIdx.x * 16;

    for (int e = tid; e < 8192; e += 256) {
        const int b = e >> 8, rem = e & 255, i = rem >> 4, c = rem & 15;
        xs[i * 512 + ((b >> 1) * 16 + c) * 2 + (b & 1)] =
            x[((size_t)b * N_ + i0 + i) * CI_ + c];
    }
    __syncthreads();

    ull tsum[16];
#pragma unroll
    for (int bp = 0; bp < 16; bp++) tsum[bp] = 0ull;

    const size_t wstride4 = (size_t)K_ * CO_ * CI_ / 4;
    const float4* wp = reinterpret_cast<const float4*>(
        W1 + (((size_t)i0 * K_ + ksrc) * CO_ + d) * CI_);

    float4 cw0 = wp[0], cw1 = wp[1], cw2 = wp[2], cw3 = wp[3];
    const float4* np1 = wp + wstride4;
    float4 nw0 = np1[0], nw1 = np1[1], nw2 = np1[2], nw3 = np1[3];

    for (int ii = 0; ii < 16; ii++) {
        float4 mw0, mw1, mw2, mw3;
        if (ii < 14) {
            const float4* np = wp + (size_t)(ii + 2) * wstride4;
            mw0 = np[0]; mw1 = np[1]; mw2 = np[2]; mw3 = np[3];
        }
        ull wd[16];
        wd[0]=pack2(cw0.x,cw0.x); wd[1]=pack2(cw0.y,cw0.y); wd[2]=pack2(cw0.z,cw0.z); wd[3]=pack2(cw0.w,cw0.w);
        wd[4]=pack2(cw1.x,cw1.x); wd[5]=pack2(cw1.y,cw1.y); wd[6]=pack2(cw1.z,cw1.z); wd[7]=pack2(cw1.w,cw1.w);
        wd[8]=pack2(cw2.x,cw2.x); wd[9]=pack2(cw2.y,cw2.y); wd[10]=pack2(cw2.z,cw2.z); wd[11]=pack2(cw2.w,cw2.w);
        wd[12]=pack2(cw3.x,cw3.x); wd[13]=pack2(cw3.y,cw3.y); wd[14]=pack2(cw3.z,cw3.z); wd[15]=pack2(cw3.w,cw3.w);

        const int i = i0 + ii;
        __half* ubase = g_uhat + (size_t)i * KD_ + kd;
#pragma unroll
        for (int bp = 0; bp < 16; bp++) {
            const ulonglong2* xq = reinterpret_cast<const ulonglong2*>(xs + ii * 512 + bp * 32);
            ulonglong2 p0 = xq[0], p1 = xq[1], p2 = xq[2], p3 = xq[3];
            ulonglong2 p4 = xq[4], p5 = xq[5], p6 = xq[6], p7 = xq[7];
            ull acc0 = 0ull, acc1 = 0ull;           // dual chains: halve dep depth
            ffma2(acc0, wd[0],  p0.x); ffma2(acc1, wd[1],  p0.y);
            ffma2(acc0, wd[2],  p1.x); ffma2(acc1, wd[3],  p1.y);
            ffma2(acc0, wd[4],  p2.x); ffma2(acc1, wd[5],  p2.y);
            ffma2(acc0, wd[6],  p3.x); ffma2(acc1, wd[7],  p3.y);
            ffma2(acc0, wd[8],  p4.x); ffma2(acc1, wd[9],  p4.y);
            ffma2(acc0, wd[10], p5.x); ffma2(acc1, wd[11], p5.y);
            ffma2(acc0, wd[12], p6.x); ffma2(acc1, wd[13], p6.y);
            ffma2(acc0, wd[14], p7.x); ffma2(acc1, wd[15], p7.y);
            fadd2(acc0, acc1);
            fadd2(tsum[bp], acc0);
            float lo, hi; unpack2(acc0, lo, hi);
            ubase[(size_t)(2 * bp)     * N_ * KD_] = __float2half_rn(lo);
            ubase[(size_t)(2 * bp + 1) * N_ * KD_] = __float2half_rn(hi);
        }
        cw0 = nw0; cw1 = nw1; cw2 = nw2; cw3 = nw3;
        nw0 = mw0; nw1 = mw1; nw2 = mw2; nw3 = mw3;
    }
#pragma unroll
    for (int bp = 0; bp < 16; bp++) {
        float a, bb; unpack2(tsum[bp], a, bb);
        atomicAdd(&g_t[0][(2 * bp)     * KD_ + kd], a);
        atomicAdd(&g_t[0][(2 * bp + 1) * KD_ + kd], bb);
    }
}

// ---------------- finalize: v[which] = squash(t * inv), vn[which] = ||v||^2 ------
__global__ void k_finalize(int which) {
    const int idx = blockIdx.x * 256 + threadIdx.x;   // b*K + k
    const float* t = g_t[which];
    float inv = (which == 0) ? (1.0f / 2048.0f) : (1.0f / g_S[0][idx]);
    const float4* tp = reinterpret_cast<const float4*>(t + idx * 16);
    float w[16]; float s2 = 0.f;
#pragma unroll
    for (int q = 0; q < 4; q++) {
        float4 tv = tp[q];
        w[q*4+0]=tv.x*inv; w[q*4+1]=tv.y*inv; w[q*4+2]=tv.z*inv; w[q*4+3]=tv.w*inv;
        s2 += w[q*4+0]*w[q*4+0] + w[q*4+1]*w[q*4+1] + w[q*4+2]*w[q*4+2] + w[q*4+3]*w[q*4+3];
    }
    float sc = sqrtf(s2) / (0.5f + s2);
    float4* vp = reinterpret_cast<float4*>(g_v[which] + idx * 16);
#pragma unroll
    for (int q = 0; q < 4; q++) {
        float4 o; o.x=sc*w[q*4+0]; o.y=sc*w[q*4+1]; o.z=sc*w[q*4+2]; o.w=sc*w[q*4+3];
        vp[q] = o;
    }
    g_vn[which][idx] = sc * sc * s2;
}

// ---------------- routing pass: half2 math, cp.async double buffer --------------
template <int IT>
__global__ void __launch_bounds__(256) k_route() {
    extern __shared__ __align__(128) char base[];
    float*   vn1 = (float*)base;                                   // 512B
    float*   vn2 = (float*)(base + 512);                           // 512B (IT3)
    char*    v1h = base + ((IT == 3) ? 1024 : 512);                // 4KB half2 v0
    char*    v2h = base + 5120;                                    // 4KB (IT3)
    __half2* cke = (__half2*)(base + ((IT == 3) ? 9216 : 4608));   // 4KB
    char*    ub  = base + ((IT == 3) ? 13312 : 8704);              // 2*32KB

    const int tid = threadIdx.x, lane = tid & 31, warp = tid >> 5;
    const int b   = blockIdx.x >> 6;
    const int ch  = blockIdx.x & 63;

    // stage v (convert fp32 -> half2), swizzled
    for (int e = tid; e < 1024; e += 256) {
        float2 f = *(const float2*)(g_v[0] + b * KD_ + 2 * e);
        *(__half2*)(v1h + SW(e * 4)) = __float22half2_rn(f);
        if (IT == 3) {
            float2 g = *(const float2*)(g_v[1] + b * KD_ + 2 * e);
            *(__half2*)(v2h + SW(e * 4)) = __float22half2_rn(g);
        }
    }
    if (tid < 128) {
        vn1[tid] = g_vn[0][b * K_ + tid];
        if (IT == 3) vn2[tid] = g_vn[1][b * K_ + tid];
    }

    const uint32_t ub_s = (uint32_t)__cvta_generic_to_shared(ub);

    // issue q=0 staging into buffer 0
    {
        const char* src = (const char*)(g_uhat + ((size_t)b * N_ + ch * 32 + warp) * KD_);
        uint32_t dst = ub_s + warp * 4096;
#pragma unroll
        for (int c = 0; c < 8; c++) {
            int off = (c * 32 + lane) * 16;
            CP_ASYNC16(dst + SW(off), src + off);
        }
        CP_COMMIT();
    }

    const int myk = warp * 16 + (lane >> 1);
    float tacc[8];
#pragma unroll
    for (int m = 0; m < 8; m++) tacc[m] = 0.f;
    float sacc = 0.f;

    int cur = 0;
    for (int q = 0; q < 4; q++) {
        CP_WAIT0();
        __syncthreads();

        if (q < 3) {
            const int inext = ch * 32 + (q + 1) * 8 + warp;
            const char* src = (const char*)(g_uhat + ((size_t)b * N_ + inext) * KD_);
            uint32_t dst = ub_s + (cur ^ 1) * 32768 + warp * 4096;
#pragma unroll
            for (int c = 0; c < 8; c++) {
                int off = (c * 32 + lane) * 16;
                CP_ASYNC16(dst + SW(off), src + off);
            }
            CP_COMMIT();
        }

        const char* msl = ub + cur * 32768 + warp * 4096;

        // ---- phase A: half2 s2/dot, fp32 squash + softmax ----
        float lg[4];
#pragma unroll
        for (int j = 0; j < 4; j++) {
            const int k = lane + 32 * j;
            uint4 r0 = *(const uint4*)(msl + SW(k * 32));
            uint4 r1 = *(const uint4*)(msl + SW(k * 32 + 16));
            uint4 w0 = *(const uint4*)(v1h + SW(k * 32));
            uint4 w1 = *(const uint4*)(v1h + SW(k * 32 + 16));
            const __half2* u0 = (const __half2*)&r0;
            const __half2* u1 = (const __half2*)&r1;
            const __half2* a0 = (const __half2*)&w0;
            const __half2* a1 = (const __half2*)&w1;
            __half2 s2h = __hmul2(u0[0], u0[0]);
            __half2 d1h = __hmul2(u0[0], a0[0]);
#pragma unroll
            for (int m = 1; m < 4; m++) {
                s2h = __hfma2(u0[m], u0[m], s2h);
                d1h = __hfma2(u0[m], a0[m], d1h);
            }
#pragma unroll
            for (int m = 0; m < 4; m++) {
                s2h = __hfma2(u1[m], u1[m], s2h);
                d1h = __hfma2(u1[m], a1[m], d1h);
            }
            float dot2 = 0.f;
            if (IT == 3) {
                uint4 y0 = *(const uint4*)(v2h + SW(k * 32));
                uint4 y1 = *(const uint4*)(v2h + SW(k * 32 + 16));
                const __half2* b0 = (const __half2*)&y0;
                const __half2* b1 = (const __half2*)&y1;
                __half2 d2h = __hmul2(u0[0], b0[0]);
#pragma unroll
                for (int m = 1; m < 4; m++) d2h = __hfma2(u0[m], b0[m], d2h);
#pragma unroll
                for (int m = 0; m < 4; m++) d2h = __hfma2(u1[m], b1[m], d2h);
                dot2 = __low2float(d2h) + __high2float(d2h);
            }
            float s2   = __low2float(s2h) + __high2float(s2h);
            float dot1 = __low2float(d1h) + __high2float(d1h);
            float sc = sqrtf(s2) / (0.5f + s2);
            float usq = sc * sc * s2;
            float dd = 1.f - (usq - 2.f * sc * dot1 + vn1[k]);
            if (IT == 3) dd += 1.f - (usq - 2.f * sc * dot2 + vn2[k]);
            lg[j] = dd;
        }
        float mx = fmaxf(fmaxf(lg[0], lg[1]), fmaxf(lg[2], lg[3]));
#pragma unroll
        for (int o = 16; o > 0; o >>= 1) mx = fmaxf(mx, __shfl_xor_sync(0xffffffffu, mx, o));
        float e0 = __expf(lg[0]-mx), e1 = __expf(lg[1]-mx), e2 = __expf(lg[2]-mx), e3 = __expf(lg[3]-mx);
        float ssum = e0 + e1 + e2 + e3;
#pragma unroll
        for (int o = 16; o > 0; o >>= 1) ssum += __shfl_xor_sync(0xffffffffu, ssum, o);
        const float invs = 1.f / ssum;
        cke[warp * 128 + lane +  0] = __float2half2_rn(__half2float(__float2half_rn(1.f)) * 0.f + e0 * invs);
        cke[warp * 128 + lane + 32] = __float2half2_rn(e1 * invs);
        cke[warp * 128 + lane + 64] = __float2half2_rn(e2 * invs);
        cke[warp * 128 + lane + 96] = __float2half2_rn(e3 * invs);

        __syncthreads();   // c + all slices ready for phase B

        // ---- phase B: half2 register accumulation over this 8-i group ----
        const char* bb = ub + cur * 32768;
        const int boff = warp * 512 + lane * 16;
        __half2 t0 = __float2half2_rn(0.f), t1 = t0, t2 = t0, t3 = t0, sh = t0;
#pragma unroll
        for (int i8 = 0; i8 < 8; i8++) {
            __half2 c2 = cke[i8 * 128 + myk];
            uint4 uv = *(const uint4*)(bb + i8 * 4096 + SW(boff));
            const __half2* u2 = (const __half2*)&uv;
            t0 = __hfma2(u2[0], c2, t0);
            t1 = __hfma2(u2[1], c2, t1);
            t2 = __hfma2(u2[2], c2, t2);
            t3 = __hfma2(u2[3], c2, t3);
            sh = __hadd2(sh, c2);
        }
        tacc[0] += __low2float(t0); tacc[1] += __high2float(t0);
        tacc[2] += __low2float(t1); tacc[3] += __high2float(t1);
        tacc[4] += __low2float(t2); tacc[5] += __high2float(t2);
        tacc[6] += __low2float(t3); tacc[7] += __high2float(t3);
        sacc += __low2float(sh);
        cur ^= 1;
    }

    float* gt = g_t[IT - 1] + b * KD_ + myk * 16 + (lane & 1) * 8;
#pragma unroll
    for (int m = 0; m < 8; m++) atomicAdd(gt + m, tacc[m]);
    if ((lane & 1) == 0) atomicAdd(&g_S[IT - 2][b * K_ + myk], sacc);
}

// ---------------- final: poses + activations -> d_out ----------------
__global__ void k_final(float* __restrict__ out) {
    const int idx = blockIdx.x * 256 + threadIdx.x;  // b*K + k
    const float inv = 1.0f / g_S[1][idx];
    const float4* tp = reinterpret_cast<const float4*>(&g_t[2][0] + idx * 16);
    float w[16]; float s2 = 0.f;
#pragma unroll
    for (int q = 0; q < 4; q++) {
        float4 tv = tp[q];
        w[q*4+0]=tv.x*inv; w[q*4+1]=tv.y*inv; w[q*4+2]=tv.z*inv; w[q*4+3]=tv.w*inv;
        s2 += w[q*4+0]*w[q*4+0] + w[q*4+1]*w[q*4+1] + w[q*4+2]*w[q*4+2] + w[q*4+3]*w[q*4+3];
    }
    float sc = sqrtf(s2) / (0.5f + s2);
    float4* op = reinterpret_cast<float4*>(out + idx * 16);
#pragma unroll
    for (int q = 0; q < 4; q++) {
        float4 o; o.x=sc*w[q*4+0]; o.y=sc*w[q*4+1]; o.z=sc*w[q*4+2]; o.w=sc*w[q*4+3];
        op[q] = o;
    }
    out[B_ * KD_ + idx] = s2 / (0.5f + s2);  // ||v||
}

// ---------------- launch ----------------
extern "C" void kernel_launch(void* const* d_in, const int* in_sizes, int n_in,
                              void* d_out, int out_size) {
    const float* x      = (const float*)d_in[0];
    const void*  labels = d_in[2];
    const float* W1     = (const float*)d_in[3];
    float*       out    = (float*)d_out;

    const int SMEM2 = 8704  + 2 * 32768;   // 74240
    const int SMEM3 = 13312 + 2 * 32768;   // 78848
    cudaFuncSetAttribute((const void*)k_route<2>, cudaFuncAttributeMaxDynamicSharedMemorySize, SMEM2);
    cudaFuncSetAttribute((const void*)k_route<3>, cudaFuncAttributeMaxDynamicSharedMemorySize, SMEM3);

    k_init<<<768, 256>>>();
    k_pass1<<<dim3(128, 8), 256>>>(x, labels, W1);
    k_finalize<<<16, 256>>>(0);               // v0 = squash(sum_i u / 2048)
    k_route<2><<<2048, 256, SMEM2>>>();       // dd(v0) -> t1, S0
    k_finalize<<<16, 256>>>(1);               // v1 = squash(t1/S0)
    k_route<3><<<2048, 256, SMEM3>>>();       // dd(v0)+dd(v1) -> t2, S1
    k_final<<<16, 256>>>(out);                // poses + activations
    (void)in_sizes; (void)n_in; (void)out_size;
}